// round 5
// baseline (speedup 1.0000x reference)
#include <cuda_runtime.h>
#include <cuda_bf16.h>
#include <cstdint>

// ============================================================================
// Problem constants: S = 256 states/vocab, B = 16 sequences, L = 512 tokens.
//
// Math: sparsemax_loss_vec(z)[y] = C(z) - z[y], C(z) = tau + 0.5*sum(p^2) + 0.5
// Backward recurrence (log semiring):
//   c_t[q] = G[x][q] + log( sum_n exp(-T[q,x,n]) * exp(c_{t+1}[n] - cmax) ) + cmax
//   G[x][q] = cE[q] - E[q,x] + cT[q,x]
// out = sum_b LSE_q( (cA - alpha[q]) + c_0[b,q] ),  c_L[q] = cOmega - omega[q]
// ============================================================================

#define SS 256
#define BB 16
#define LL 512
#define CLUSTER 8

// -------- device scratch (static: no allocations allowed) --------
__device__ float          g_cT[SS * SS];          // C(T[q,x,:]) indexed [q*256+x]
__device__ float          g_cE[SS];
__device__ float          g_Gtab[SS * SS];        // [x][q]
__device__ float          g_c0[SS];               // cOmega - omega[q]
__device__ float          g_LAl[SS];              // cAlpha - alpha[q]
__device__ __nv_bfloat16  g_M[(size_t)SS * SS * SS]; // [x][next][q] = exp(-T[q,x,next])
__device__ float          g_perseq[BB];

// -------- helpers --------
__device__ __forceinline__ float wredMax(float v) {
#pragma unroll
    for (int o = 16; o; o >>= 1) v = fmaxf(v, __shfl_xor_sync(0xffffffffu, v, o));
    return v;
}
__device__ __forceinline__ float wredSum(float v) {
#pragma unroll
    for (int o = 16; o; o >>= 1) v += __shfl_xor_sync(0xffffffffu, v, o);
    return v;
}

// exp(x) without MUFU (used 16.7M times in the transpose kernel; EX2 would be
// throughput-bound at ~120us). |x| here is <= ~0.8 so n in {-2..2}; poly on
// t in [-0.347, 0.347], remainder ~2e-8.
__device__ __forceinline__ float exp_poly(float x) {
    float y = x * 1.44269504088896341f;
    float n = rintf(y);
    float t = (y - n) * 0.6931471805599453f;
    float p = 1.98412698412698413e-4f;            // 1/5040
    p = fmaf(p, t, 1.38888888888888889e-3f);      // 1/720
    p = fmaf(p, t, 8.33333333333333333e-3f);      // 1/120
    p = fmaf(p, t, 4.16666666666666667e-2f);      // 1/24
    p = fmaf(p, t, 1.66666666666666667e-1f);      // 1/6
    p = fmaf(p, t, 0.5f);
    p = fmaf(p, t, 1.0f);
    p = fmaf(p, t, 1.0f);
    return p * __int_as_float(((int)n + 127) << 23);
}

// C(z) for a 256-length row held as 8 regs/lane (lane i owns z[4i..4i+3],
// z[128+4i..128+4i+3]). tau found by bisection on f(tau)=sum relu(z-tau)-1
// (strictly decreasing, tau in [zmax-1, zmax]). All lanes return same value.
__device__ __forceinline__ float sparse_c8(const float v[8]) {
    float zmax = v[0];
#pragma unroll
    for (int i = 1; i < 8; i++) zmax = fmaxf(zmax, v[i]);
    zmax = wredMax(zmax);
    float lo = zmax - 1.0f, hi = zmax;
#pragma unroll 1
    for (int it = 0; it < 26; ++it) {
        float tau = 0.5f * (lo + hi);
        float s = 0.0f;
#pragma unroll
        for (int i = 0; i < 8; i++) s += fmaxf(v[i] - tau, 0.0f);
        s = wredSum(s);
        if (s > 1.0f) lo = tau; else hi = tau;
    }
    float tau = 0.5f * (lo + hi);
    float s2 = 0.0f;
#pragma unroll
    for (int i = 0; i < 8; i++) {
        float p = fmaxf(v[i] - tau, 0.0f);
        s2 = fmaf(p, p, s2);
    }
    s2 = wredSum(s2);
    return tau + 0.5f * s2 + 0.5f;
}

__device__ __forceinline__ void load_row8(const float* __restrict__ z, int lane, float v[8]) {
    const float4* z4 = reinterpret_cast<const float4*>(z);
    float4 a = z4[lane];
    float4 b = z4[lane + 32];
    v[0] = a.x; v[1] = a.y; v[2] = a.z; v[3] = a.w;
    v[4] = b.x; v[5] = b.y; v[6] = b.z; v[7] = b.w;
}

// -------- K1: per-row C for all 65536 rows of T --------
__global__ void __launch_bounds__(256) k_rowconst_T(const float* __restrict__ T) {
    int warp = (blockIdx.x * blockDim.x + threadIdx.x) >> 5;   // row id = q*256+x
    int lane = threadIdx.x & 31;
    float v[8];
    load_row8(T + (size_t)warp * SS, lane, v);
    float c = sparse_c8(v);
    if (lane == 0) g_cT[warp] = c;
}

// -------- K2: C for E rows, alpha, omega --------
__global__ void __launch_bounds__(256) k_small(const float* __restrict__ E,
                                               const float* __restrict__ al,
                                               const float* __restrict__ om) {
    int warp = (blockIdx.x * blockDim.x + threadIdx.x) >> 5;
    int lane = threadIdx.x & 31;
    float v[8];
    if (warp < SS) {
        load_row8(E + (size_t)warp * SS, lane, v);
        float c = sparse_c8(v);
        if (lane == 0) g_cE[warp] = c;
    } else if (warp == SS) {
        load_row8(al, lane, v);
        float c = sparse_c8(v);
#pragma unroll
        for (int i = 0; i < 8; i++) g_LAl[lane + 32 * i] = c - al[lane + 32 * i];
    } else if (warp == SS + 1) {
        load_row8(om, lane, v);
        float c = sparse_c8(v);
#pragma unroll
        for (int i = 0; i < 8; i++) g_c0[lane + 32 * i] = c - om[lane + 32 * i];
    }
}

// -------- K3: G[x][q] = cE[q] - E[q,x] + cT[q,x] --------
__global__ void __launch_bounds__(256) k_gtab(const float* __restrict__ E) {
    int x = blockIdx.x, q = threadIdx.x;
    g_Gtab[x * SS + q] = g_cE[q] - E[q * SS + x] + g_cT[q * SS + x];
}

// -------- K4: M[x][n][q] = bf16(exp(-T[q][x][n])) via tiled smem transpose --------
__global__ void __launch_bounds__(256) k_buildM(const float* __restrict__ T) {
    __shared__ float tile[32][33];
    int x  = blockIdx.z;
    int q0 = blockIdx.x << 5, n0 = blockIdx.y << 5;
    int tx = threadIdx.x, ty = threadIdx.y;
#pragma unroll
    for (int i = 0; i < 32; i += 8) {
        int q = q0 + ty + i;
        tile[ty + i][tx] = T[(unsigned)q * 65536u + (unsigned)x * 256u + n0 + tx];
    }
    __syncthreads();
#pragma unroll
    for (int i = 0; i < 32; i += 8) {
        int n = n0 + ty + i;
        g_M[(size_t)x * 65536u + (size_t)n * 256u + q0 + tx] =
            __float2bfloat16(exp_poly(-tile[tx][ty + i]));
    }
}

// -------- DSMEM store to a peer CTA's shared memory --------
__device__ __forceinline__ void st_remote(unsigned local_smem, unsigned target_rank, float v) {
    unsigned remote;
    asm volatile("mapa.shared::cluster.u32 %0, %1, %2;"
                 : "=r"(remote) : "r"(local_smem), "r"(target_rank));
    asm volatile("st.shared::cluster.f32 [%0], %1;" :: "r"(remote), "f"(v) : "memory");
}
__device__ __forceinline__ unsigned smem_u32(const void* p) {
    return (unsigned)__cvta_generic_to_shared(p);
}
__device__ __forceinline__ void cluster_sync_() {
    asm volatile("barrier.cluster.arrive.aligned;" ::: "memory");
    asm volatile("barrier.cluster.wait.aligned;"   ::: "memory");
}

// -------- K5: main backward recursion. One 8-CTA cluster per batch. --------
// CTA rank r owns q in [32r, 32r+32). Double-buffered chart (256 vals + 8
// per-rank maxes) lives in every CTA's smem, refreshed each step via DSMEM;
// exactly one cluster barrier per step.
__global__ void __cluster_dims__(CLUSTER, 1, 1) __launch_bounds__(256, 1)
k_forward(const int* __restrict__ xs) {
    __shared__ float sbuf[2][SS + 8];   // chart + 8 chunk maxes, double buffered
    __shared__ float se[SS];            // exp(c - cmax)
    __shared__ float spart[8][32];      // per-warp-group partial dots
    __shared__ int   sx[LL];
    __shared__ float sG[SS * 32];       // G[x][q0+l] for all x, local q chunk

    const int tid  = threadIdx.x;
    const int lane = tid & 31, wid = tid >> 5;
    const unsigned rank = (unsigned)(blockIdx.x & (CLUSTER - 1));
    const int b  = blockIdx.x >> 3;
    const int q0 = (int)rank * 32;

    for (int i = tid; i < LL; i += 256) sx[i] = xs[b * LL + i];
    for (int i = tid; i < SS * 32; i += 256) {
        int x = i >> 5, l = i & 31;
        sG[i] = g_Gtab[x * SS + q0 + l];
    }
    sbuf[0][tid] = g_c0[tid];
    if (tid < 8) {
        float m = -3.0e38f;
#pragma unroll
        for (int i = 0; i < 32; i++) m = fmaxf(m, g_c0[tid * 32 + i]);
        sbuf[0][SS + tid] = m;
    }
    __syncthreads();
    cluster_sync_();

    const __nv_bfloat16* __restrict__ mbase = g_M;

    for (int s = 0; s < LL; ++s) {
        const int p = s & 1, np = p ^ 1;
        const int x = sx[LL - 1 - s];

        // cmax from the 8 chunk maxes (redundant per-thread; smem broadcast)
        float cmax = sbuf[p][SS];
#pragma unroll
        for (int i = 1; i < 8; i++) cmax = fmaxf(cmax, sbuf[p][SS + i]);

        se[tid] = __expf(sbuf[p][tid] - cmax);
        __syncthreads();

        // warp-group wid covers next = wid + 8j; lanes cover the 32 local q's
        float acc = 0.0f;
        const __nv_bfloat16* mp = mbase + ((unsigned)x << 16) + ((unsigned)wid << 8) + q0 + lane;
#pragma unroll
        for (int j = 0; j < 32; j++) {
            float m = __bfloat162float(__ldg(mp + ((unsigned)j << 11)));
            acc = fmaf(m, se[wid + (j << 3)], acc);
        }
        spart[wid][lane] = acc;
        __syncthreads();

        // every warp redundantly reduces (so each warp can ship to one peer)
        float ssum = spart[0][lane];
#pragma unroll
        for (int g = 1; g < 8; g++) ssum += spart[g][lane];

        float nc;
        if (x != 0)
            nc = sG[(x << 5) + lane] + __logf(ssum) + cmax;
        else
            nc = sbuf[p][q0 + lane];           // padding: chart passes through
        float mx = wredMax(nc);

        st_remote(smem_u32(&sbuf[np][q0 + lane]), (unsigned)wid, nc);
        if (lane == 0)
            st_remote(smem_u32(&sbuf[np][SS + rank]), (unsigned)wid, mx);

        cluster_sync_();
    }

    // final chart is in sbuf[0] (512 steps, last write flips to buffer 0)
    if (rank == 0 && wid == 0) {
        float vv[8];
        float m = -3.0e38f;
#pragma unroll
        for (int i = 0; i < 8; i++) {
            vv[i] = g_LAl[lane + 32 * i] + sbuf[0][lane + 32 * i];
            m = fmaxf(m, vv[i]);
        }
        m = wredMax(m);
        float s = 0.0f;
#pragma unroll
        for (int i = 0; i < 8; i++) s += __expf(vv[i] - m);
        s = wredSum(s);
        if (lane == 0) g_perseq[b] = __logf(s) + m;
    }
}

// -------- K6: out = sum_b per_seq[b] --------
__global__ void k_final(float* __restrict__ out) {
    float v = (threadIdx.x < BB) ? g_perseq[threadIdx.x] : 0.0f;
    v = wredSum(v);
    if (threadIdx.x == 0) out[0] = v;
}

// ============================================================================
extern "C" void kernel_launch(void* const* d_in, const int* in_sizes, int n_in,
                              void* d_out, int out_size) {
    const int*   xs    = (const int*)d_in[0];
    const float* alpha = (const float*)d_in[1];
    const float* omega = (const float*)d_in[2];
    const float* E     = (const float*)d_in[3];
    const float* T     = (const float*)d_in[4];
    float* out = (float*)d_out;

    k_rowconst_T<<<(SS * SS) / 8, 256>>>(T);            // 65536 warps
    k_small<<<33, 256>>>(E, alpha, omega);              // 258 row-consts
    k_gtab<<<SS, 256>>>(E);
    k_buildM<<<dim3(8, 8, SS), dim3(32, 8)>>>(T);       // exp(-T) transpose -> bf16
    k_forward<<<BB * CLUSTER, 256>>>(xs);               // 16 clusters x 8 CTAs
    k_final<<<1, 32>>>(out);
}

// round 6
// speedup vs baseline: 1.1479x; 1.1479x over previous
#include <cuda_runtime.h>
#include <cuda_bf16.h>
#include <cstdint>

// ============================================================================
// S = 256 states/vocab, B = 16 sequences, L = 512 tokens.
// sparsemax_loss_vec(z)[y] = C(z) - z[y], C(z) = tau + 0.5*sum(p^2) + 0.5
// Backward recurrence (log semiring):
//   c_t[q] = G[x][q] + log( sum_n exp(-T[q,x,n]) * exp(c_{t+1}[n] - cmax) ) + cmax
//   G[x][q] = cE[q] - E[q,x] + cT[q,x]
// out = sum_b LSE_q( (cA - alpha[q]) + c_0[b,q] ),  c_L[q] = cOmega - omega[q]
// ============================================================================

#define SS 256
#define BB 16
#define LL 512
#define CLUSTER 8

// -------- device scratch --------
__device__ float          g_cT[SS * SS];
__device__ float          g_cE[SS];
__device__ float          g_Gtab[SS * SS];            // [x][q]
__device__ float          g_c0[SS];
__device__ float          g_LAl[SS];
__device__ __nv_bfloat16  g_M[(size_t)SS * SS * SS];  // [x][next][q] = exp(-T[q,x,next])
__device__ float          g_perseq[BB];

// -------- helpers --------
__device__ __forceinline__ float wredMax(float v) {
#pragma unroll
    for (int o = 16; o; o >>= 1) v = fmaxf(v, __shfl_xor_sync(0xffffffffu, v, o));
    return v;
}
__device__ __forceinline__ float wredSum(float v) {
#pragma unroll
    for (int o = 16; o; o >>= 1) v += __shfl_xor_sync(0xffffffffu, v, o);
    return v;
}

// MUFU-free exp (|x| <= ~0.8 here)
__device__ __forceinline__ float exp_poly(float x) {
    float y = x * 1.44269504088896341f;
    float n = rintf(y);
    float t = (y - n) * 0.6931471805599453f;
    float p = 1.98412698412698413e-4f;
    p = fmaf(p, t, 1.38888888888888889e-3f);
    p = fmaf(p, t, 8.33333333333333333e-3f);
    p = fmaf(p, t, 4.16666666666666667e-2f);
    p = fmaf(p, t, 1.66666666666666667e-1f);
    p = fmaf(p, t, 0.5f);
    p = fmaf(p, t, 1.0f);
    p = fmaf(p, t, 1.0f);
    return p * __int_as_float(((int)n + 127) << 23);
}

// C(z) via bisection. NB: C is stationary in tau at the solution (dC/dtau =
// 1 - sum p = 0), so tau error eps gives C error O(k*eps^2): 14 iters suffice.
template <int ITERS>
__device__ __forceinline__ float sparse_c8(const float v[8]) {
    float zmax = v[0];
#pragma unroll
    for (int i = 1; i < 8; i++) zmax = fmaxf(zmax, v[i]);
    zmax = wredMax(zmax);
    float lo = zmax - 1.0f, hi = zmax;
#pragma unroll 1
    for (int it = 0; it < ITERS; ++it) {
        float tau = 0.5f * (lo + hi);
        float s = 0.0f;
#pragma unroll
        for (int i = 0; i < 8; i++) s += fmaxf(v[i] - tau, 0.0f);
        s = wredSum(s);
        if (s > 1.0f) lo = tau; else hi = tau;
    }
    float tau = 0.5f * (lo + hi);
    float s2 = 0.0f;
#pragma unroll
    for (int i = 0; i < 8; i++) {
        float p = fmaxf(v[i] - tau, 0.0f);
        s2 = fmaf(p, p, s2);
    }
    s2 = wredSum(s2);
    return tau + 0.5f * s2 + 0.5f;
}

__device__ __forceinline__ void load_row8(const float* __restrict__ z, int lane, float v[8]) {
    const float4* z4 = reinterpret_cast<const float4*>(z);
    float4 a = z4[lane];
    float4 b = z4[lane + 32];
    v[0] = a.x; v[1] = a.y; v[2] = a.z; v[3] = a.w;
    v[4] = b.x; v[5] = b.y; v[6] = b.z; v[7] = b.w;
}

// -------- K1: per-row C for all 65536 rows of T --------
__global__ void __launch_bounds__(256) k_rowconst_T(const float* __restrict__ T) {
    int warp = (blockIdx.x * blockDim.x + threadIdx.x) >> 5;
    int lane = threadIdx.x & 31;
    float v[8];
    load_row8(T + (size_t)warp * SS, lane, v);
    float c = sparse_c8<14>(v);
    if (lane == 0) g_cT[warp] = c;
}

// -------- K2: C for E rows, alpha, omega --------
__global__ void __launch_bounds__(256) k_small(const float* __restrict__ E,
                                               const float* __restrict__ al,
                                               const float* __restrict__ om) {
    int warp = (blockIdx.x * blockDim.x + threadIdx.x) >> 5;
    int lane = threadIdx.x & 31;
    float v[8];
    if (warp < SS) {
        load_row8(E + (size_t)warp * SS, lane, v);
        float c = sparse_c8<26>(v);
        if (lane == 0) g_cE[warp] = c;
    } else if (warp == SS) {
        load_row8(al, lane, v);
        float c = sparse_c8<26>(v);
#pragma unroll
        for (int i = 0; i < 8; i++) g_LAl[lane + 32 * i] = c - al[lane + 32 * i];
    } else if (warp == SS + 1) {
        load_row8(om, lane, v);
        float c = sparse_c8<26>(v);
#pragma unroll
        for (int i = 0; i < 8; i++) g_c0[lane + 32 * i] = c - om[lane + 32 * i];
    }
}

// -------- K3: G[x][q] --------
__global__ void __launch_bounds__(256) k_gtab(const float* __restrict__ E) {
    int x = blockIdx.x, q = threadIdx.x;
    g_Gtab[x * SS + q] = g_cE[q] - E[q * SS + x] + g_cT[q * SS + x];
}

// -------- K4: M[x][n][q] = bf16(exp(-T[q][x][n])) --------
__global__ void __launch_bounds__(256) k_buildM(const float* __restrict__ T) {
    __shared__ float tile[32][33];
    int x  = blockIdx.z;
    int q0 = blockIdx.x << 5, n0 = blockIdx.y << 5;
    int tx = threadIdx.x, ty = threadIdx.y;
#pragma unroll
    for (int i = 0; i < 32; i += 8) {
        int q = q0 + ty + i;
        tile[ty + i][tx] = T[(unsigned)q * 65536u + (unsigned)x * 256u + n0 + tx];
    }
    __syncthreads();
#pragma unroll
    for (int i = 0; i < 32; i += 8) {
        int n = n0 + ty + i;
        g_M[(size_t)x * 65536u + (size_t)n * 256u + q0 + tx] =
            __float2bfloat16(exp_poly(-tile[tx][ty + i]));
    }
}

// -------- cluster primitives --------
__device__ __forceinline__ unsigned smem_u32(const void* p) {
    return (unsigned)__cvta_generic_to_shared(p);
}
__device__ __forceinline__ unsigned mapa_u32(unsigned local_smem, unsigned target_rank) {
    unsigned remote;
    asm volatile("mapa.shared::cluster.u32 %0, %1, %2;"
                 : "=r"(remote) : "r"(local_smem), "r"(target_rank));
    return remote;
}
__device__ __forceinline__ void cluster_sync_() {
    asm volatile("barrier.cluster.arrive.aligned;" ::: "memory");
    asm volatile("barrier.cluster.wait.aligned;"   ::: "memory");
}
__device__ __forceinline__ void mbar_wait_acq(unsigned addr, unsigned parity) {
    asm volatile(
        "{\n\t.reg .pred P;\n\t"
        "WAITLOOP_%=:\n\t"
        "mbarrier.try_wait.parity.acquire.cluster.shared::cta.b64 P, [%0], %1, 0x989680;\n\t"
        "@P bra.uni WAITDONE_%=;\n\t"
        "bra.uni WAITLOOP_%=;\n\t"
        "WAITDONE_%=:\n\t}"
        :: "r"(addr), "r"(parity) : "memory");
}

// -------- K5: main backward recursion. One 8-CTA cluster per batch. --------
// CTA rank r owns q in [32r,32r+32). Full chart replicated in every CTA.
// Per step: mbarrier full-barrier (count 8, parity-cycled, double-buffered
// charts), M prefetched one step ahead into registers, cmax := chart[0]
// (any ballpark shift is numerically valid for the LSE).
__global__ void __cluster_dims__(CLUSTER, 1, 1) __launch_bounds__(256, 1)
k_forward(const int* __restrict__ xs) {
    __shared__ float sbuf[2][SS];                 // replicated chart, double buffered
    __shared__ __align__(16) float se2[2][8 * 36]; // warp-grouped exp(c - cmax)
    __shared__ float spart[8][32];
    __shared__ int   sx[LL];
    __shared__ float sG[SS * 32];
    __shared__ __align__(8) unsigned long long smbar[2];

    const int tid  = threadIdx.x;
    const int lane = tid & 31, wid = tid >> 5;
    const unsigned rank = (unsigned)(blockIdx.x & (CLUSTER - 1));
    const int b  = blockIdx.x >> 3;
    const int q0 = (int)rank * 32;

    for (int i = tid; i < LL; i += 256) sx[i] = xs[b * LL + i];
    for (int i = tid; i < SS * 32; i += 256) {
        int x = i >> 5, l = i & 31;
        sG[i] = g_Gtab[x * SS + q0 + l];
    }
    sbuf[0][tid] = g_c0[tid];
    if (tid == 0) {
        asm volatile("mbarrier.init.shared.b64 [%0], %1;"
                     :: "r"(smem_u32(&smbar[0])), "r"(8) : "memory");
        asm volatile("mbarrier.init.shared.b64 [%0], %1;"
                     :: "r"(smem_u32(&smbar[1])), "r"(8) : "memory");
    }
    __syncthreads();
    cluster_sync_();   // all init + mbarriers visible cluster-wide

    // warp w ships the CTA's q-chunk + arrival to peer CTA w
    const unsigned bar0_loc  = smem_u32(&smbar[0]);
    const unsigned bar_rem0  = mapa_u32(smem_u32(&smbar[0]), (unsigned)wid);
    const unsigned bar_rem1  = mapa_u32(smem_u32(&smbar[1]), (unsigned)wid);
    const unsigned ch_rem0   = mapa_u32(smem_u32(&sbuf[0][q0 + lane]), (unsigned)wid);
    const unsigned ch_rem1   = mapa_u32(smem_u32(&sbuf[1][q0 + lane]), (unsigned)wid);

    unsigned short mA[32], mB[32];

#define PREFETCH(dst, xval) do {                                                   \
    const unsigned short* _mp = (const unsigned short*)g_M                         \
        + (((unsigned)(xval)) << 16) + ((unsigned)wid << 8) + (unsigned)(q0+lane); \
    _Pragma("unroll")                                                              \
    for (int _j = 0; _j < 32; _j++) dst[_j] = __ldg(_mp + (_j << 11));             \
} while (0)

    // All sbuf[P] reads are hoisted BEFORE the first __syncthreads: this makes
    // the 2-buffer scheme safe against 1-step cross-CTA warp skew (a peer can
    // only reach its end-of-(s+1) remote writes into sbuf[P] after every local
    // warp passed this step's barriers, i.e. after these reads completed).
#define STEP_COMPUTE(P, CUR, CHREM, BARREM, XV) do {                               \
    const int _x = (XV);                                                           \
    float cmax  = sbuf[P][0];                                                      \
    float c     = sbuf[P][tid];                                                    \
    float cpass = sbuf[P][q0 + lane];                                              \
    se2[P][(tid & 7) * 36 + (tid >> 3)] = __expf(c - cmax);                        \
    __syncthreads();                                                               \
    float a0 = 0.f, a1 = 0.f, a2 = 0.f, a3 = 0.f;                                  \
    const float4* _sv4 = (const float4*)&se2[P][wid * 36];                         \
    _Pragma("unroll")                                                              \
    for (int _j = 0; _j < 8; _j++) {                                               \
        float4 _sv = _sv4[_j];                                                     \
        a0 = fmaf(__uint_as_float((unsigned)CUR[4*_j+0] << 16), _sv.x, a0);        \
        a1 = fmaf(__uint_as_float((unsigned)CUR[4*_j+1] << 16), _sv.y, a1);        \
        a2 = fmaf(__uint_as_float((unsigned)CUR[4*_j+2] << 16), _sv.z, a2);        \
        a3 = fmaf(__uint_as_float((unsigned)CUR[4*_j+3] << 16), _sv.w, a3);        \
    }                                                                              \
    spart[wid][lane] = (a0 + a1) + (a2 + a3);                                      \
    __syncthreads();                                                               \
    float ssum = 0.f;                                                              \
    _Pragma("unroll")                                                              \
    for (int _g = 0; _g < 8; _g++) ssum += spart[_g][lane];                        \
    float nc = (_x != 0) ? (sG[(_x << 5) + lane] + __logf(ssum) + cmax) : cpass;   \
    asm volatile("st.shared::cluster.f32 [%0], %1;"                                \
                 :: "r"(CHREM), "f"(nc) : "memory");                               \
    __syncwarp();                                                                  \
    if (lane == 0)                                                                 \
        asm volatile("mbarrier.arrive.release.cluster.shared::cluster.b64 _, [%0];"\
                     :: "r"(BARREM) : "memory");                                   \
} while (0)

    { int x0 = sx[LL - 1]; PREFETCH(mA, x0); }

    unsigned ph0 = 0, ph1 = 0;
#pragma unroll 1
    for (int s = 0; s < LL; s += 2) {
        // even step s: reads sbuf[0], writes peers' sbuf[1], arrives mbar[1]
        {
            int xn = sx[LL - 2 - s];                 // x for step s+1 (s <= 510)
            PREFETCH(mB, xn);
            if (s) { mbar_wait_acq(bar0_loc, ph0); ph0 ^= 1; }
            STEP_COMPUTE(0, mA, ch_rem1, bar_rem1, sx[LL - 1 - s]);
        }
        // odd step s+1: reads sbuf[1], writes peers' sbuf[0], arrives mbar[0]
        {
            int xn = (s + 2 < LL) ? sx[LL - 3 - s] : 0;  // dummy ok at the end
            PREFETCH(mA, xn);
            mbar_wait_acq(smem_u32(&smbar[1]), ph1); ph1 ^= 1;
            STEP_COMPUTE(1, mB, ch_rem0, bar_rem0, sx[LL - 2 - s]);
        }
    }
    // consume the arrivals of step 511 (writes into sbuf[0]) in every CTA
    mbar_wait_acq(bar0_loc, ph0);

    if (rank == 0 && wid == 0) {
        float vv[8];
        float m = -3.0e38f;
#pragma unroll
        for (int i = 0; i < 8; i++) {
            vv[i] = g_LAl[lane + 32 * i] + sbuf[0][lane + 32 * i];
            m = fmaxf(m, vv[i]);
        }
        m = wredMax(m);
        float s = 0.0f;
#pragma unroll
        for (int i = 0; i < 8; i++) s += __expf(vv[i] - m);
        s = wredSum(s);
        if (lane == 0) g_perseq[b] = __logf(s) + m;
    }
    cluster_sync_();   // no CTA exits while remote ops may target it
#undef PREFETCH
#undef STEP_COMPUTE
}

// -------- K6: out = sum_b per_seq[b] --------
__global__ void k_final(float* __restrict__ out) {
    float v = (threadIdx.x < BB) ? g_perseq[threadIdx.x] : 0.0f;
    v = wredSum(v);
    if (threadIdx.x == 0) out[0] = v;
}

// ============================================================================
extern "C" void kernel_launch(void* const* d_in, const int* in_sizes, int n_in,
                              void* d_out, int out_size) {
    const int*   xs    = (const int*)d_in[0];
    const float* alpha = (const float*)d_in[1];
    const float* omega = (const float*)d_in[2];
    const float* E     = (const float*)d_in[3];
    const float* T     = (const float*)d_in[4];
    float* out = (float*)d_out;

    k_rowconst_T<<<(SS * SS) / 8, 256>>>(T);
    k_small<<<33, 256>>>(E, alpha, omega);
    k_gtab<<<SS, 256>>>(E);
    k_buildM<<<dim3(8, 8, SS), dim3(32, 8)>>>(T);
    k_forward<<<BB * CLUSTER, 256>>>(xs);
    k_final<<<1, 32>>>(out);
}